// round 5
// baseline (speedup 1.0000x reference)
#include <cuda_runtime.h>

#define Nn 4096
#define Dd 128
#define H1h 256

typedef unsigned long long u64;

// ---------------- device scratch ------------------------------------------
__device__ __align__(16) float g_Wt [Dd*Dd];
__device__ __align__(16) float g_M  [Dd*Dd];
__device__ __align__(16) float g_P2[Dd*Dd],  g_P3[Dd*Dd],  g_P4[Dd*Dd],  g_P7[Dd*Dd];
__device__ __align__(16) float g_P8[Dd*Dd],  g_P15[Dd*Dd], g_P16[Dd*Dd], g_P31[Dd*Dd];
__device__ __align__(16) float g_P32[Dd*Dd], g_P63[Dd*Dd], g_P64[Dd*Dd], g_P127[Dd*Dd];
__device__ float g_s2[H1h];
__device__ float g_B2;
__device__ float g_regP[128];
__device__ __align__(16) float g_y [Nn*Dd];
__device__ float g_T [Dd*256];
__device__ float g_Pa[Dd*257];
__device__ float g_Pb[Dd*257];

// grid barrier (sense-reversal, replay-safe)
__device__ volatile unsigned g_gen = 0;
__device__ unsigned g_cnt = 0;

// ---------------- packed f32x2 helpers ------------------------------------
__device__ __forceinline__ u64 pk2(float lo, float hi){
    u64 r; asm("mov.b64 %0, {%1, %2};" : "=l"(r) : "f"(lo), "f"(hi)); return r;
}
__device__ __forceinline__ void upk2(u64 v, float& lo, float& hi){
    asm("mov.b64 {%0, %1}, %2;" : "=f"(lo), "=f"(hi) : "l"(v));
}
__device__ __forceinline__ u64 fma2(u64 a, u64 b, u64 c){
    u64 d; asm("fma.rn.f32x2 %0, %1, %2, %3;" : "=l"(d) : "l"(a), "l"(b), "l"(c));
    return d;
}

__device__ __forceinline__ void gridbar(){
    __syncthreads();
    __threadfence();
    if (threadIdx.x == 0){
        unsigned g = g_gen;
        if (atomicAdd(&g_cnt, 1) == gridDim.x - 1){
            g_cnt = 0;
            __threadfence();
            g_gen = g + 1;
        } else {
            while (g_gen == g) { }
        }
    }
    __syncthreads();
}

// ---------------- prep: distributed over 128 blocks ------------------------
__global__ void prep_kernel(const float* __restrict__ weight,
                            const float* __restrict__ A,
                            const float* __restrict__ W2,
                            const float* __restrict__ b2,
                            float* __restrict__ d_out)
{
    __shared__ float red[256];
    int t = threadIdx.x, b = blockIdx.x;   // 128 blocks x 256 threads
    float labs = 0.f;
    if (t < 128){
        int idx = b*128 + t;
        float w = weight[idx] * A[idx];
        int r = idx >> 7, c = idx & 127;
        g_Wt[c*Dd + r] = w;
        g_M[idx] = (r == c ? 1.f : 0.f) + (w*w)*(1.f/128.f);
        labs = fabsf(w);
    }
    // s2: rows 2b, 2b+1 via warps 0,1 (same warp-shfl arithmetic as before)
    {
        int w = t >> 5, lane = t & 31;
        if (w < 2){
            int row = b*2 + w;
            const float* p = W2 + row*128;
            float v = (p[lane] + p[lane+32]) + (p[lane+64] + p[lane+96]);
            #pragma unroll
            for (int s = 16; s > 0; s >>= 1)
                v += __shfl_xor_sync(0xffffffffu, v, s);
            if (lane == 0) g_s2[row] = v;
        }
    }
    // B2 in block 0
    if (b == 0){
        red[t] = (t < 128) ? b2[t] : 0.f;
        __syncthreads();
        for (int s = 128; s > 0; s >>= 1){
            if (t < s) red[t] += red[t + s];
            __syncthreads();
        }
        if (t == 0) g_B2 = red[0];
        __syncthreads();
    }
    // reg: block partial -> gridbar -> block0 tree
    red[t] = labs;
    __syncthreads();
    for (int s = 128; s > 0; s >>= 1){
        if (t < s) red[t] += red[t + s];
        __syncthreads();
    }
    if (t == 0) g_regP[b] = red[0];
    gridbar();
    if (b == 0){
        red[t] = (t < 128) ? g_regP[t] : 0.f;
        __syncthreads();
        for (int s = 128; s > 0; s >>= 1){
            if (t < s) red[t] += red[t + s];
            __syncthreads();
        }
        if (t == 0) d_out[Nn*Dd + 1] = red[0];
    }
}

// ---- ladder: smem-staged R (transposed, pad 132), bit-identical chains ----
#define RT_PITCH 132

__device__ __forceinline__ void load_rt(float* Rt, const float* Rm, int t){
    const float4* R4 = (const float4*)Rm;
    #pragma unroll
    for (int idx = t; idx < 4096; idx += 256){
        float4 v = __ldcg(R4 + idx);
        int k  = idx >> 5;
        int j4 = (idx & 31) << 2;
        Rt[(j4+0)*RT_PITCH + k] = v.x;
        Rt[(j4+1)*RT_PITCH + k] = v.y;
        Rt[(j4+2)*RT_PITCH + k] = v.z;
        Rt[(j4+3)*RT_PITCH + k] = v.w;
    }
}

// single-acc ascending-k chain (identical value sequence to passing version)
__device__ __forceinline__ float chain(const float* Lrow, const float* Rt, int j){
    const float4* c4 = (const float4*)(Rt + j*RT_PITCH);
    const float4* l4 = (const float4*)Lrow;
    float acc = 0.f;
    #pragma unroll
    for (int k4 = 0; k4 < 32; k4++){
        float4 rv = c4[k4];
        float4 lv = l4[k4];
        acc = fmaf(lv.x, rv.x, acc);
        acc = fmaf(lv.y, rv.y, acc);
        acc = fmaf(lv.z, rv.z, acc);
        acc = fmaf(lv.w, rv.w, acc);
    }
    return acc;
}

__global__ void ladder_kernel(float* __restrict__ d_out)
{
    extern __shared__ __align__(16) float sm[];
    float* Rt = sm;                      // 128 * 132
    float* Ls = sm + 128*RT_PITCH;       // 256
    int t = threadIdx.x, bid = blockIdx.x;

    #define LEVEL1(L, R, D)                                               \
    {                                                                     \
        load_rt(Rt, R, t);                                                \
        if (t < 128) Ls[t] = __ldcg(&L[bid*128 + t]);                     \
        __syncthreads();                                                  \
        if (t < 128) D[bid*128 + t] = chain(Ls, Rt, t);                   \
        gridbar();                                                        \
    }
    #define LEVEL2(LA, RA, DA, LB, RB, DB)                                \
    {                                                                     \
        const float* Rm = (bid >> 6) ? RB : RA;                           \
        const float* Lm = (bid >> 6) ? LB : LA;                           \
        float*       Dm = (bid >> 6) ? DB : DA;                           \
        int rb = (bid & 63)*2;                                            \
        load_rt(Rt, Rm, t);                                               \
        Ls[t] = __ldcg(&Lm[rb*128 + t]);                                  \
        __syncthreads();                                                  \
        Dm[(rb + (t>>7))*128 + (t & 127)]                                 \
            = chain(Ls + (t>>7)*128, Rt, t & 127);                        \
        gridbar();                                                        \
    }

    LEVEL1(g_M,   g_M,   g_P2 )
    LEVEL2(g_M,   g_P2,  g_P3 ,  g_P2,  g_P2,  g_P4 )
    LEVEL2(g_P3,  g_P4,  g_P7 ,  g_P4,  g_P4,  g_P8 )
    LEVEL2(g_P7,  g_P8,  g_P15,  g_P8,  g_P8,  g_P16)
    LEVEL2(g_P15, g_P16, g_P31,  g_P16, g_P16, g_P32)
    LEVEL2(g_P31, g_P32, g_P63,  g_P32, g_P32, g_P64)
    LEVEL1(g_P63, g_P64, g_P127)

    // hsum: identical arithmetic to passing version
    if (bid == 0 && t < 32){
        __shared__ float p[32];
        int l = t;
        float s = 0.f;
        for (int it = 0; it < 512; it++){
            int idx = l + (it << 5);
            int i = idx >> 7, jj = idx & 127;
            s += __ldcg(&g_P127[jj*128 + i]) * __ldcg(&g_M[i*128 + jj]);
        }
        p[l] = s;
        __syncwarp();
        for (int st = 16; st > 0; st >>= 1){
            if (l < st) p[l] += p[l + st];
            __syncwarp();
        }
        if (l == 0) d_out[Nn*Dd] = p[0] - 128.f;
    }
}

// ---------------- y = x @ W + bias (unchanged, passing) --------------------
__global__ void gemm_kernel(const float* __restrict__ x,
                            const float* __restrict__ bias)
{
    __shared__ __align__(16) float xs[32][128];
    int t  = threadIdx.x;
    int n0 = blockIdx.x * 32;
    for (int idx = t; idx < 32*128; idx += 256)
        xs[idx >> 7][idx & 127] = x[n0*128 + idx];
    __syncthreads();

    int i  = t & 127;
    int ng = t >> 7;
    const u64* wrow = (const u64*)(g_Wt + i*128);
    u64 acc[16];
    #pragma unroll
    for (int u = 0; u < 16; u++) acc[u] = 0ULL;

    for (int d2 = 0; d2 < 64; d2 += 2){
        u64 w01 = wrow[d2];
        u64 w23 = wrow[d2 + 1];
        #pragma unroll
        for (int u = 0; u < 16; u++){
            const u64* xp = (const u64*)&xs[ng*16 + u][d2*2];
            acc[u] = fma2(xp[0], w01, acc[u]);
            acc[u] = fma2(xp[1], w23, acc[u]);
        }
    }
    float bi = bias[i];
    #pragma unroll
    for (int u = 0; u < 16; u++){
        float p, q; upk2(acc[u], p, q);
        g_y[(n0 + ng*16 + u)*Dd + i] = (p + q) + bi;
    }
}

// ---- fsetup (unchanged, passing) ------------------------------------------
__global__ void fsetup_kernel(const float* __restrict__ W1,
                              const float* __restrict__ b1)
{
    __shared__ float key[256]; __shared__ int sidx[256];
    __shared__ float asA[256], bsA[256];
    __shared__ int   upA[256];
    __shared__ float UA[256], UB[256], DA[256], DB[256];
    __shared__ float red[256];

    int i = blockIdx.x, t = threadIdx.x;
    float a = W1[i*H1h + t];
    float b = b1[t];
    float s = g_s2[t];
    float as = a*s, bs = b*s;
    float tb; int up; float c0 = 0.f;
    if (a > 0.f)      { tb = -b/a; up = 1; }
    else if (a < 0.f) { tb = -b/a; up = 0; }
    else { tb = __int_as_float(0x7f800000); up = 1; as = 0.f; bs = 0.f;
           c0 = fmaxf(b, 0.f) * s; }

    key[t] = tb; sidx[t] = t;
    asA[t] = as; bsA[t] = bs; upA[t] = up;
    __syncthreads();

    for (int ksz = 2; ksz <= 256; ksz <<= 1){
        for (int jsz = ksz >> 1; jsz > 0; jsz >>= 1){
            int ixj = t ^ jsz;
            float k0 = key[t], k1 = key[ixj];
            int   i0 = sidx[t], i1 = sidx[ixj];
            __syncthreads();
            if (ixj > t){
                bool asc = ((t & ksz) == 0);
                bool sw  = asc ? (k0 > k1) : (k0 < k1);
                if (sw){ key[t] = k1; key[ixj] = k0;
                         sidx[t] = i1; sidx[ixj] = i0; }
            }
            __syncthreads();
        }
    }

    int o = sidx[t];
    float pas = asA[o], pbs = bsA[o];
    int pup = upA[o];
    UA[t] = pup ? pas : 0.f;  UB[t] = pup ? pbs : 0.f;
    DA[t] = pup ? 0.f : pas;  DB[t] = pup ? 0.f : pbs;
    __syncthreads();

    for (int off = 1; off < 256; off <<= 1){
        float ua = (t >= off) ? UA[t-off] : 0.f;
        float ub = (t >= off) ? UB[t-off] : 0.f;
        float da = (t >= off) ? DA[t-off] : 0.f;
        float db = (t >= off) ? DB[t-off] : 0.f;
        __syncthreads();
        UA[t] += ua; UB[t] += ub; DA[t] += da; DB[t] += db;
        __syncthreads();
    }

    red[t] = c0;
    __syncthreads();
    for (int st = 128; st > 0; st >>= 1){
        if (t < st) red[t] += red[t + st];
        __syncthreads();
    }
    float C0 = red[0] + g_B2;
    float totDA = DA[255], totDB = DB[255];

    float exUA = (t > 0) ? UA[t-1] : 0.f;
    float exUB = (t > 0) ? UB[t-1] : 0.f;
    float exDA = (t > 0) ? DA[t-1] : 0.f;
    float exDB = (t > 0) ? DB[t-1] : 0.f;

    g_T [i*256 + t] = key[t];
    g_Pa[i*257 + t] = exUA + (totDA - exDA);
    g_Pb[i*257 + t] = exUB + (totDB - exDB) + C0;
    if (t == 255){
        g_Pa[i*257 + 256] = UA[255];
        g_Pb[i*257 + 256] = UB[255] + C0;
    }
}

// ---- feval: 16-col tiles, 256 blocks, 8 interleaved searches/thread -------
__global__ void feval_kernel(float* __restrict__ d_out)
{
    extern __shared__ float dyn[];
    float* sT  = dyn;              // [16][257]
    float* sPa = sT  + 16*257;
    float* sPb = sPa + 16*257;

    int t  = threadIdx.x;          // 256
    int i0 = (blockIdx.x & 7)  * 16;
    int n0 = (blockIdx.x >> 3) * 128;

    for (int idx = t; idx < 16*257; idx += 256){
        int ii = idx / 257, kk = idx - ii*257;
        sT [idx] = (kk < 256) ? g_T[(i0+ii)*256 + kk] : __int_as_float(0x7f800000);
        sPa[idx] = g_Pa[(i0+ii)*257 + kk];
        sPb[idx] = g_Pb[(i0+ii)*257 + kk];
    }
    __syncthreads();

    int li = t & 15, rg = t >> 4;        // 16 i x 16 row-groups
    const float* Tl  = sT  + li*257;
    const float* Pal = sPa + li*257;
    const float* Pbl = sPb + li*257;

    float yv[8];
    int   kk[8];
    #pragma unroll
    for (int p = 0; p < 8; p++){
        yv[p] = g_y[(n0 + rg + p*16)*Dd + i0 + li];
        kk[p] = 0;
    }
    #pragma unroll
    for (int stp = 128; stp > 0; stp >>= 1){
        #pragma unroll
        for (int p = 0; p < 8; p++)
            if (Tl[kk[p] + stp - 1] < yv[p]) kk[p] += stp;
    }
    #pragma unroll
    for (int p = 0; p < 8; p++)
        d_out[(n0 + rg + p*16)*Dd + i0 + li] = fmaf(yv[p], Pal[kk[p]], Pbl[kk[p]]);
}

// ---------------- launch ----------------------------------------------------
extern "C" void kernel_launch(void* const* d_in, const int* in_sizes, int n_in,
                              void* d_out, int out_size)
{
    (void)in_sizes; (void)n_in; (void)out_size;
    const float* x      = (const float*)d_in[0];
    const float* weight = (const float*)d_in[1];
    const float* bias   = (const float*)d_in[2];
    const float* A      = (const float*)d_in[3];
    const float* W1     = (const float*)d_in[4];
    const float* b1     = (const float*)d_in[5];
    const float* W2     = (const float*)d_in[6];
    const float* b2     = (const float*)d_in[7];
    float* out = (float*)d_out;

    const int FEVAL_SMEM  = 3*16*257*(int)sizeof(float);
    const int LADDER_SMEM = (128*RT_PITCH + 256)*(int)sizeof(float);

    static bool attr_done = false;
    if (!attr_done){
        cudaFuncSetAttribute(feval_kernel,
                             cudaFuncAttributeMaxDynamicSharedMemorySize, FEVAL_SMEM);
        cudaFuncSetAttribute(ladder_kernel,
                             cudaFuncAttributeMaxDynamicSharedMemorySize, LADDER_SMEM);
        attr_done = true;
    }

    prep_kernel  <<<128, 256>>>(weight, A, W2, b2, out);
    fsetup_kernel<<<128, 256>>>(W1, b1);
    gemm_kernel  <<<128, 256>>>(x, bias);
    feval_kernel <<<256, 256, FEVAL_SMEM>>>(out);
    ladder_kernel<<<128, 256, LADDER_SMEM>>>(out);
}

// round 7
// speedup vs baseline: 1.3836x; 1.3836x over previous
#include <cuda_runtime.h>

#define Nn 4096
#define Dd 128
#define H1h 256

typedef unsigned long long u64;

// ---------------- device scratch ------------------------------------------
__device__ __align__(16) float g_Wt [Dd*Dd];
__device__ __align__(16) float g_M  [Dd*Dd];
__device__ __align__(16) float g_P2[Dd*Dd],  g_P3[Dd*Dd],  g_P4[Dd*Dd],  g_P7[Dd*Dd];
__device__ __align__(16) float g_P8[Dd*Dd],  g_P15[Dd*Dd], g_P16[Dd*Dd], g_P31[Dd*Dd];
__device__ __align__(16) float g_P32[Dd*Dd], g_P63[Dd*Dd], g_P64[Dd*Dd], g_P127[Dd*Dd];
__device__ float g_s2[H1h];
__device__ float g_B2;
__device__ float g_regP[128];
__device__ __align__(16) float g_y [Nn*Dd];
__device__ float g_T [Dd*256];
__device__ float g_Pa[Dd*257];
__device__ float g_Pb[Dd*257];

// grid barrier (sense-reversal, replay-safe) — ONLY used in 128-block grids
__device__ volatile unsigned g_gen = 0;
__device__ unsigned g_cnt = 0;

// ---------------- packed f32x2 helpers ------------------------------------
__device__ __forceinline__ u64 pk2(float lo, float hi){
    u64 r; asm("mov.b64 %0, {%1, %2};" : "=l"(r) : "f"(lo), "f"(hi)); return r;
}
__device__ __forceinline__ void upk2(u64 v, float& lo, float& hi){
    asm("mov.b64 {%0, %1}, %2;" : "=f"(lo), "=f"(hi) : "l"(v));
}
__device__ __forceinline__ u64 fma2(u64 a, u64 b, u64 c){
    u64 d; asm("fma.rn.f32x2 %0, %1, %2, %3;" : "=l"(d) : "l"(a), "l"(b), "l"(c));
    return d;
}

__device__ __forceinline__ void gridbar(){
    __syncthreads();
    __threadfence();
    if (threadIdx.x == 0){
        unsigned g = g_gen;
        if (atomicAdd(&g_cnt, 1) == gridDim.x - 1){
            g_cnt = 0;
            __threadfence();
            g_gen = g + 1;
        } else {
            while (g_gen == g) { }
        }
    }
    __syncthreads();
}

// ======== kernel 1: prep (distributed) + fsetup, fused (128 blocks) ========
__global__ void __launch_bounds__(256, 1)
prepsetup_kernel(const float* __restrict__ weight,
                 const float* __restrict__ A,
                 const float* __restrict__ W2,
                 const float* __restrict__ b2,
                 const float* __restrict__ W1,
                 const float* __restrict__ b1,
                 float* __restrict__ d_out)
{
    __shared__ float red[256];
    __shared__ float key[256]; __shared__ int sidx[256];
    __shared__ float asA[256], bsA[256];
    __shared__ int   upA[256];
    __shared__ float UA[256], UB[256], DA[256], DB[256];

    int t = threadIdx.x, b = blockIdx.x;   // 128 blocks x 256 threads
    // ---- prep part ----
    float labs = 0.f;
    if (t < 128){
        int idx = b*128 + t;
        float w = weight[idx] * A[idx];
        int r = idx >> 7, c = idx & 127;
        g_Wt[c*Dd + r] = w;
        g_M[idx] = (r == c ? 1.f : 0.f) + (w*w)*(1.f/128.f);
        labs = fabsf(w);
    }
    {
        int w = t >> 5, lane = t & 31;
        if (w < 2){
            int row = b*2 + w;
            const float* p = W2 + row*128;
            float v = (p[lane] + p[lane+32]) + (p[lane+64] + p[lane+96]);
            #pragma unroll
            for (int s = 16; s > 0; s >>= 1)
                v += __shfl_xor_sync(0xffffffffu, v, s);
            if (lane == 0) g_s2[row] = v;
        }
    }
    if (b == 0){
        red[t] = (t < 128) ? b2[t] : 0.f;
        __syncthreads();
        for (int s = 128; s > 0; s >>= 1){
            if (t < s) red[t] += red[t + s];
            __syncthreads();
        }
        if (t == 0) g_B2 = red[0];
        __syncthreads();
    }
    red[t] = labs;
    __syncthreads();
    for (int s = 128; s > 0; s >>= 1){
        if (t < s) red[t] += red[t + s];
        __syncthreads();
    }
    if (t == 0) g_regP[b] = red[0];
    gridbar();                                 // s2/B2/regP now global-visible
    if (b == 0){
        red[t] = (t < 128) ? g_regP[t] : 0.f;
        __syncthreads();
        for (int s = 128; s > 0; s >>= 1){
            if (t < s) red[t] += red[t + s];
            __syncthreads();
        }
        if (t == 0) d_out[Nn*Dd + 1] = red[0];
    }
    __syncthreads();

    // ---- fsetup part: block b handles column i = b ----
    int i = b;
    float a = W1[i*H1h + t];
    float bb = b1[t];
    float s = __ldcg(&g_s2[t]);
    float as = a*s, bs = bb*s;
    float tb; int up; float c0 = 0.f;
    if (a > 0.f)      { tb = -bb/a; up = 1; }
    else if (a < 0.f) { tb = -bb/a; up = 0; }
    else { tb = __int_as_float(0x7f800000); up = 1; as = 0.f; bs = 0.f;
           c0 = fmaxf(bb, 0.f) * s; }

    key[t] = tb; sidx[t] = t;
    asA[t] = as; bsA[t] = bs; upA[t] = up;
    __syncthreads();

    for (int ksz = 2; ksz <= 256; ksz <<= 1){
        for (int jsz = ksz >> 1; jsz > 0; jsz >>= 1){
            int ixj = t ^ jsz;
            float k0 = key[t], k1 = key[ixj];
            int   i0 = sidx[t], i1 = sidx[ixj];
            __syncthreads();
            if (ixj > t){
                bool asc = ((t & ksz) == 0);
                bool sw  = asc ? (k0 > k1) : (k0 < k1);
                if (sw){ key[t] = k1; key[ixj] = k0;
                         sidx[t] = i1; sidx[ixj] = i0; }
            }
            __syncthreads();
        }
    }

    int o = sidx[t];
    float pas = asA[o], pbs = bsA[o];
    int pup = upA[o];
    UA[t] = pup ? pas : 0.f;  UB[t] = pup ? pbs : 0.f;
    DA[t] = pup ? 0.f : pas;  DB[t] = pup ? 0.f : pbs;
    __syncthreads();

    for (int off = 1; off < 256; off <<= 1){
        float ua = (t >= off) ? UA[t-off] : 0.f;
        float ub = (t >= off) ? UB[t-off] : 0.f;
        float da = (t >= off) ? DA[t-off] : 0.f;
        float db = (t >= off) ? DB[t-off] : 0.f;
        __syncthreads();
        UA[t] += ua; UB[t] += ub; DA[t] += da; DB[t] += db;
        __syncthreads();
    }

    red[t] = c0;
    __syncthreads();
    for (int st = 128; st > 0; st >>= 1){
        if (t < st) red[t] += red[t + st];
        __syncthreads();
    }
    float C0 = red[0] + __ldcg(&g_B2);
    float totDA = DA[255], totDB = DB[255];

    float exUA = (t > 0) ? UA[t-1] : 0.f;
    float exUB = (t > 0) ? UB[t-1] : 0.f;
    float exDA = (t > 0) ? DA[t-1] : 0.f;
    float exDB = (t > 0) ? DB[t-1] : 0.f;

    g_T [i*256 + t] = key[t];
    g_Pa[i*257 + t] = exUA + (totDA - exDA);
    g_Pb[i*257 + t] = exUB + (totDB - exDB) + C0;
    if (t == 255){
        g_Pa[i*257 + 256] = UA[255];
        g_Pb[i*257 + 256] = UB[255] + C0;
    }
}

// ======== kernel 2: y = x @ W + bias (128 blocks, unchanged math) ==========
__global__ void __launch_bounds__(256)
gemm_kernel(const float* __restrict__ x, const float* __restrict__ bias)
{
    __shared__ __align__(16) float xs[32][128];
    int t  = threadIdx.x;
    int n0 = blockIdx.x * 32;
    for (int idx = t; idx < 32*128; idx += 256)
        xs[idx >> 7][idx & 127] = x[n0*128 + idx];
    __syncthreads();

    int i  = t & 127;
    int ng = t >> 7;
    const u64* wrow = (const u64*)(g_Wt + i*128);
    u64 acc[16];
    #pragma unroll
    for (int u = 0; u < 16; u++) acc[u] = 0ULL;

    for (int d2 = 0; d2 < 64; d2 += 2){
        u64 w01 = wrow[d2];
        u64 w23 = wrow[d2 + 1];
        #pragma unroll
        for (int u = 0; u < 16; u++){
            const u64* xp = (const u64*)&xs[ng*16 + u][d2*2];
            acc[u] = fma2(xp[0], w01, acc[u]);
            acc[u] = fma2(xp[1], w23, acc[u]);
        }
    }
    float bi = bias[i];
    #pragma unroll
    for (int u = 0; u < 16; u++){
        float p, q; upk2(acc[u], p, q);
        g_y[(n0 + ng*16 + u)*Dd + i] = (p + q) + bi;
    }
}

// ======== kernel 3: feval (512 blocks, no barrier — any occupancy OK) ======
#define FEVAL_I 8
__global__ void __launch_bounds__(256)
feval_kernel(float* __restrict__ d_out)
{
    extern __shared__ float dyn[];
    float* sT  = dyn;                       // [8][257]
    float* sPa = sT  + FEVAL_I*257;
    float* sPb = sPa + FEVAL_I*257;

    int t  = threadIdx.x;
    int i0 = (blockIdx.x & 15) * FEVAL_I;   // 16 i-tiles
    int n0 = (blockIdx.x >> 4) * 128;       // 32 n-tiles

    for (int idx = t; idx < FEVAL_I*257; idx += 256){
        int ii = idx / 257, kk = idx - ii*257;
        sT [idx] = (kk < 256) ? g_T[(i0+ii)*256 + kk] : __int_as_float(0x7f800000);
        sPa[idx] = g_Pa[(i0+ii)*257 + kk];
        sPb[idx] = g_Pb[(i0+ii)*257 + kk];
    }
    __syncthreads();

    int li = t & 7, rg = t >> 3;            // 8 i x 32 row-groups
    const float* Tl  = sT  + li*257;
    const float* Pal = sPa + li*257;
    const float* Pbl = sPb + li*257;

    float yv[4];
    int   kk[4];
    #pragma unroll
    for (int p = 0; p < 4; p++){
        yv[p] = g_y[(n0 + rg + p*32)*Dd + i0 + li];
        kk[p] = 0;
    }
    #pragma unroll
    for (int stp = 128; stp > 0; stp >>= 1){
        #pragma unroll
        for (int p = 0; p < 4; p++)
            if (Tl[kk[p] + stp - 1] < yv[p]) kk[p] += stp;
    }
    #pragma unroll
    for (int p = 0; p < 4; p++)
        d_out[(n0 + rg + p*32)*Dd + i0 + li] = fmaf(yv[p], Pal[kk[p]], Pbl[kk[p]]);
}

// ======== kernel 4: ladder (128 blocks, row-major smem, conflict-free) =====
__device__ __forceinline__ void load_r(float* Rt, const float* Rm, int t){
    const float4* R4 = (const float4*)Rm;
    float4* S4 = (float4*)Rt;
    #pragma unroll
    for (int idx = t; idx < 4096; idx += 256)
        S4[idx] = __ldcg(R4 + idx);        // straight copy: [k][j] row-major
}

// single-acc ascending-k chain — value sequence identical to passing version
__device__ __forceinline__ float chain(const float* Ls, const float* Rt, int j){
    float acc = 0.f;
    #pragma unroll
    for (int k = 0; k < 128; k++)
        acc = fmaf(Ls[k], Rt[k*128 + j], acc);
    return acc;
}

__global__ void __launch_bounds__(256, 1)
ladder_kernel(float* __restrict__ d_out)
{
    extern __shared__ __align__(16) float sm[];
    float* Rt = sm;                      // 128*128
    float* Ls = sm + 128*128;            // 256
    int t = threadIdx.x, bid = blockIdx.x;

    #define LEVEL1(L, R, D)                                               \
    {                                                                     \
        load_r(Rt, R, t);                                                 \
        if (t < 128) Ls[t] = __ldcg(&L[bid*128 + t]);                     \
        __syncthreads();                                                  \
        if (t < 128) D[bid*128 + t] = chain(Ls, Rt, t);                   \
        gridbar();                                                        \
    }
    #define LEVEL2(LA, RA, DA, LB, RB, DB)                                \
    {                                                                     \
        const float* Rm = (bid >> 6) ? RB : RA;                           \
        const float* Lm = (bid >> 6) ? LB : LA;                           \
        float*       Dm = (bid >> 6) ? DB : DA;                           \
        int rb = (bid & 63)*2;                                            \
        load_r(Rt, Rm, t);                                                \
        Ls[t] = __ldcg(&Lm[rb*128 + t]);                                  \
        __syncthreads();                                                  \
        Dm[(rb + (t>>7))*128 + (t & 127)]                                 \
            = chain(Ls + (t>>7)*128, Rt, t & 127);                        \
        gridbar();                                                        \
    }

    LEVEL1(g_M,   g_M,   g_P2 )
    LEVEL2(g_M,   g_P2,  g_P3 ,  g_P2,  g_P2,  g_P4 )
    LEVEL2(g_P3,  g_P4,  g_P7 ,  g_P4,  g_P4,  g_P8 )
    LEVEL2(g_P7,  g_P8,  g_P15,  g_P8,  g_P8,  g_P16)
    LEVEL2(g_P15, g_P16, g_P31,  g_P16, g_P16, g_P32)
    LEVEL2(g_P31, g_P32, g_P63,  g_P32, g_P32, g_P64)
    LEVEL1(g_P63, g_P64, g_P127)

    // hsum: identical arithmetic to passing version
    if (bid == 0 && t < 32){
        __shared__ float p[32];
        int l = t;
        float s = 0.f;
        for (int it = 0; it < 512; it++){
            int idx = l + (it << 5);
            int i = idx >> 7, jj = idx & 127;
            s += __ldcg(&g_P127[jj*128 + i]) * __ldcg(&g_M[i*128 + jj]);
        }
        p[l] = s;
        __syncwarp();
        for (int st = 16; st > 0; st >>= 1){
            if (l < st) p[l] += p[l + st];
            __syncwarp();
        }
        if (l == 0) d_out[Nn*Dd] = p[0] - 128.f;
    }
}

// ---------------- launch ----------------------------------------------------
extern "C" void kernel_launch(void* const* d_in, const int* in_sizes, int n_in,
                              void* d_out, int out_size)
{
    (void)in_sizes; (void)n_in; (void)out_size;
    const float* x      = (const float*)d_in[0];
    const float* weight = (const float*)d_in[1];
    const float* bias   = (const float*)d_in[2];
    const float* A      = (const float*)d_in[3];
    const float* W1     = (const float*)d_in[4];
    const float* b1     = (const float*)d_in[5];
    const float* W2     = (const float*)d_in[6];
    const float* b2     = (const float*)d_in[7];
    float* out = (float*)d_out;

    const int FEVAL_SMEM  = 3*FEVAL_I*257*(int)sizeof(float);   // 24672
    const int LADDER_SMEM = (128*128 + 256)*(int)sizeof(float); // 66560

    static bool attr_done = false;
    if (!attr_done){
        cudaFuncSetAttribute(feval_kernel,
                             cudaFuncAttributeMaxDynamicSharedMemorySize, FEVAL_SMEM);
        cudaFuncSetAttribute(ladder_kernel,
                             cudaFuncAttributeMaxDynamicSharedMemorySize, LADDER_SMEM);
        attr_done = true;
    }

    prepsetup_kernel<<<128, 256>>>(weight, A, W2, b2, W1, b1, out);
    gemm_kernel     <<<128, 256>>>(x, bias);
    feval_kernel    <<<512, 256, FEVAL_SMEM>>>(out);
    ladder_kernel   <<<128, 256, LADDER_SMEM>>>(out);
}